// round 1
// baseline (speedup 1.0000x reference)
#include <cuda_runtime.h>
#include <math.h>

#define NN   16384
#define HD   128
#define EE   524288
#define EDD  16
#define HID  256
#define EPSB 1e-5f
#define NEG  0.01f
#define CAP  256
#define RW   8

// ---------------- scratch (device globals; no allocation) ----------------
__device__ float g_Q[NN*HD];
__device__ float g_K[NN*HD];
__device__ float g_V[NN*HD];
__device__ float g_eb[EE];
__device__ int   g_hist[NN];
__device__ int   g_fill[NN];
__device__ int   g_rowstart[NN+1];
__device__ int   g_cdst[EE];
__device__ float g_cs[EE];
__device__ float g_Vsum[HD];
__device__ float g_h0[NN*HD];
__device__ float g_f1[NN*HID];
__device__ float g_h2[NN*HD];
__device__ float g_sum1[HD], g_sq1[HD], g_scale1[HD], g_shift1[HD];
__device__ float g_sum2[HD], g_sq2[HD], g_scale2[HD], g_shift2[HD];
__device__ int   g_notI64;   // 1 if edge_index is int32

// ---------------- helpers ----------------
__device__ __forceinline__ int ld_idx(const long long* ei, int i) {
    return g_notI64 ? ((const int*)ei)[i] : (int)ei[i];
}

// ---------------- zero scratch ----------------
__global__ void k_zero() {
    int i = blockIdx.x * blockDim.x + threadIdx.x;
    int stride = gridDim.x * blockDim.x;
    for (int j = i; j < NN; j += stride) { g_hist[j] = 0; g_fill[j] = 0; }
    if (i < HD) {
        g_Vsum[i] = 0.f;
        g_sum1[i] = 0.f; g_sq1[i] = 0.f;
        g_sum2[i] = 0.f; g_sq2[i] = 0.f;
    }
    if (i == 0) g_notI64 = 0;
}

// ---------------- detect edge_index dtype ----------------
__global__ void k_detect(const long long* __restrict__ ei) {
    int i = blockIdx.x * blockDim.x + threadIdx.x;
    long long v = ei[i];               // reading EE int64 is in-bounds either way
    if (v < 0 || v > (NN - 1)) g_notI64 = 1;
}

// ---------------- generic tiled fp32 GEMM ----------------
// C[M,Ncols] = op(A[M,K]) @ B[K,Ncols] + bias ; A-transform per-k (BN), epilogues
__global__ __launch_bounds__(256) void k_gemm(
    const float* __restrict__ A, const float* __restrict__ B,
    const float* __restrict__ bias, float* __restrict__ C,
    int M, int Ncols, int K,
    const float* __restrict__ sA, const float* __restrict__ hA,
    int epi, const float* __restrict__ resH0,
    const float* __restrict__ rs, const float* __restrict__ rh)
{
    __shared__ float As[16][64];
    __shared__ float Bs[16][64];
    int t = threadIdx.x;
    int tx = t & 15, ty = t >> 4;
    int row0 = blockIdx.y * 64, col0 = blockIdx.x * 64;
    float acc[4][4] = {};
    int ar = t >> 2, ak = (t & 3) * 4;
    int bk = t >> 4, bn = (t & 15) * 4;

    for (int k0 = 0; k0 < K; k0 += 16) {
        float4 av = *(const float4*)&A[(row0 + ar) * K + k0 + ak];
        if (sA) {
            av.x = av.x * sA[k0+ak  ] + hA[k0+ak  ];
            av.y = av.y * sA[k0+ak+1] + hA[k0+ak+1];
            av.z = av.z * sA[k0+ak+2] + hA[k0+ak+2];
            av.w = av.w * sA[k0+ak+3] + hA[k0+ak+3];
        }
        As[ak  ][ar] = av.x;
        As[ak+1][ar] = av.y;
        As[ak+2][ar] = av.z;
        As[ak+3][ar] = av.w;
        float4 bv = *(const float4*)&B[(k0 + bk) * Ncols + col0 + bn];
        *(float4*)&Bs[bk][bn] = bv;
        __syncthreads();
#pragma unroll
        for (int k = 0; k < 16; k++) {
            float4 a = *(const float4*)&As[k][ty * 4];
            float4 b = *(const float4*)&Bs[k][tx * 4];
            acc[0][0] += a.x*b.x; acc[0][1] += a.x*b.y; acc[0][2] += a.x*b.z; acc[0][3] += a.x*b.w;
            acc[1][0] += a.y*b.x; acc[1][1] += a.y*b.y; acc[1][2] += a.y*b.z; acc[1][3] += a.y*b.w;
            acc[2][0] += a.z*b.x; acc[2][1] += a.z*b.y; acc[2][2] += a.z*b.z; acc[2][3] += a.z*b.w;
            acc[3][0] += a.w*b.x; acc[3][1] += a.w*b.y; acc[3][2] += a.w*b.z; acc[3][3] += a.w*b.w;
        }
        __syncthreads();
    }
#pragma unroll
    for (int i = 0; i < 4; i++) {
        int r = row0 + ty * 4 + i;
#pragma unroll
        for (int j = 0; j < 4; j++) {
            int c = col0 + tx * 4 + j;
            float v = acc[i][j] + bias[c];
            if (epi == 1) v = fmaxf(v, 0.f);
            else if (epi == 2) v += resH0[r * HD + c] * rs[c] + rh[c];
            C[r * Ncols + c] = v;
        }
    }
}

// ---------------- edge bias + src histogram ----------------
__global__ void k_ebias_hist(const float* __restrict__ ea, const float* __restrict__ We,
                             const float* __restrict__ be, const long long* __restrict__ ei)
{
    int e = blockIdx.x * blockDim.x + threadIdx.x;
    if (e >= EE) return;
    const float4* a4 = (const float4*)(ea + (size_t)e * EDD);
    float s = be[0];
#pragma unroll
    for (int i = 0; i < 4; i++) {
        float4 v = a4[i];
        s += v.x * We[i*4] + v.y * We[i*4+1] + v.z * We[i*4+2] + v.w * We[i*4+3];
    }
    g_eb[e] = s;
    int src = ld_idx(ei, e);
    atomicAdd(&g_hist[src], 1);
}

// ---------------- exclusive scan over 16384 counts ----------------
__global__ void k_scan() {
    __shared__ int ps[1024];
    int t = threadIdx.x;
    int base = t * 16;
    int loc[16]; int s = 0;
#pragma unroll
    for (int i = 0; i < 16; i++) { loc[i] = g_hist[base + i]; s += loc[i]; }
    ps[t] = s;
    __syncthreads();
    for (int off = 1; off < 1024; off <<= 1) {
        int v = (t >= off) ? ps[t - off] : 0;
        __syncthreads();
        ps[t] += v;
        __syncthreads();
    }
    int run = ps[t] - s;
#pragma unroll
    for (int i = 0; i < 16; i++) { g_rowstart[base + i] = run; run += loc[i]; }
    if (t == 1023) g_rowstart[NN] = run;
}

// ---------------- column sum of V ----------------
__global__ void k_vsum() {
    int c = threadIdx.x;
    int b = blockIdx.x;
    float s = 0.f;
    for (int r = b * 128; r < (b + 1) * 128; r++) s += g_V[r * HD + c];
    atomicAdd(&g_Vsum[c], s);
}

// ---------------- per-edge score + scatter into CSR ----------------
__global__ __launch_bounds__(256) void k_score(const long long* __restrict__ ei) {
    int w = threadIdx.x >> 5, lane = threadIdx.x & 31;
    int e = blockIdx.x * 8 + w;
    int src = ld_idx(ei, e);
    int dst = ld_idx(ei, EE + e);
    float4 q = *(const float4*)&g_Q[src * HD + lane * 4];
    float4 k = *(const float4*)&g_K[dst * HD + lane * 4];
    float p = q.x*k.x + q.y*k.y + q.z*k.z + q.w*k.w;
#pragma unroll
    for (int o = 16; o; o >>= 1) p += __shfl_xor_sync(0xffffffffu, p, o);
    if (lane == 0) {
        float s = p + g_eb[e];
        s = (s >= 0.f) ? s : NEG * s;
        int pos = g_rowstart[src] + atomicAdd(&g_fill[src], 1);
        g_cdst[pos] = dst;
        g_cs[pos]   = s;
    }
}

// ---------------- per-row dedup + softmax + V gather -> h0 = x + x_new ------
__global__ __launch_bounds__(256) void k_row(const float* __restrict__ x) {
    __shared__ int   sd[RW][CAP];
    __shared__ float ss[RW][CAP];
    __shared__ int   sf[RW][CAP];
    int w = threadIdx.x >> 5, lane = threadIdx.x & 31;
    int row = blockIdx.x * RW + w;
    int start = g_rowstart[row], end = g_rowstart[row + 1];
    int k = end - start;
    const float4* V4 = (const float4*)g_V;
    float4 acc;
    float invden;

    if (k <= CAP) {
        for (int i = lane; i < k; i += 32) { sd[w][i] = g_cdst[start + i]; ss[w][i] = g_cs[start + i]; }
        __syncwarp();
        for (int i = lane; i < k; i += 32) {
            int d = sd[w][i]; int f = 0;
            while (sd[w][f] != d) f++;
            sf[w][i] = f;
        }
        __syncwarp();
        for (int i = lane; i < k; i += 32)
            if (sf[w][i] != i) atomicAdd(&ss[w][sf[w][i]], ss[w][i]);
        __syncwarp();
        float m = 0.f; int cnt = 0;
        for (int i = lane; i < k; i += 32)
            if (sf[w][i] == i) { m = fmaxf(m, ss[w][i]); cnt++; }
#pragma unroll
        for (int o = 16; o; o >>= 1) {
            m = fmaxf(m, __shfl_xor_sync(0xffffffffu, m, o));
            cnt += __shfl_xor_sync(0xffffffffu, cnt, o);
        }
        float em = expf(-m);
        float sumExp = 0.f;
        for (int i = lane; i < k; i += 32) {
            float wv = 0.f;
            if (sf[w][i] == i) {
                float e1 = expf(ss[w][i] - m);
                sumExp += e1;
                wv = e1 - em;
            }
            ss[w][i] = wv;
        }
        __syncwarp();
#pragma unroll
        for (int o = 16; o; o >>= 1) sumExp += __shfl_xor_sync(0xffffffffu, sumExp, o);
        float denom = sumExp + (float)(NN - cnt) * em;
        invden = 1.f / denom;
        float4 vs = ((const float4*)g_Vsum)[lane];
        acc.x = em * vs.x; acc.y = em * vs.y; acc.z = em * vs.z; acc.w = em * vs.w;
        for (int i = 0; i < k; i++) {
            float wv = ss[w][i];           // uniform broadcast
            if (wv != 0.f) {
                float4 v = V4[sd[w][i] * 32 + lane];
                acc.x += wv * v.x; acc.y += wv * v.y; acc.z += wv * v.z; acc.w += wv * v.w;
            }
        }
    } else {
        // ultra-rare fallback: O(k^2), warp-uniform, no scratch
        float m = 0.f; int cnt = 0;
        for (int i = 0; i < k; i++) {
            int d = g_cdst[start + i];
            bool first = true; float v = 0.f;
            for (int j = 0; j < k; j++) {
                int dj = g_cdst[start + j];
                if (dj == d) { if (j < i) { first = false; break; } v += g_cs[start + j]; }
            }
            if (first) { cnt++; m = fmaxf(m, v); }
        }
        float em = expf(-m);
        float sumExp = 0.f;
        float4 vs = ((const float4*)g_Vsum)[lane];
        acc.x = em * vs.x; acc.y = em * vs.y; acc.z = em * vs.z; acc.w = em * vs.w;
        for (int i = 0; i < k; i++) {
            int d = g_cdst[start + i];
            bool first = true; float v = 0.f;
            for (int j = 0; j < k; j++) {
                int dj = g_cdst[start + j];
                if (dj == d) { if (j < i) { first = false; break; } v += g_cs[start + j]; }
            }
            if (first) {
                float e1 = expf(v - m);
                sumExp += e1;
                float wv = e1 - em;
                float4 vv = V4[d * 32 + lane];
                acc.x += wv * vv.x; acc.y += wv * vv.y; acc.z += wv * vv.z; acc.w += wv * vv.w;
            }
        }
        float denom = sumExp + (float)(NN - cnt) * em;
        invden = 1.f / denom;
    }

    float4 xr = ((const float4*)x)[row * 32 + lane];
    float4 o;
    o.x = xr.x + acc.x * invden;
    o.y = xr.y + acc.y * invden;
    o.z = xr.z + acc.z * invden;
    o.w = xr.w + acc.w * invden;
    ((float4*)g_h0)[row * 32 + lane] = o;
}

// ---------------- batchnorm column stats ----------------
__global__ void k_stats(const float* __restrict__ src, float* __restrict__ osum, float* __restrict__ osq) {
    __shared__ float sh1[128], sh2[128];
    int t = threadIdx.x;
    int c = t & 127, half = t >> 7;
    int r0 = blockIdx.x * 128 + half;
    float s = 0.f, q = 0.f;
    for (int i = 0; i < 64; i++) {
        float v = src[(r0 + 2 * i) * HD + c];
        s += v; q += v * v;
    }
    if (half) { sh1[c] = s; sh2[c] = q; }
    __syncthreads();
    if (!half) {
        atomicAdd(&osum[c], s + sh1[c]);
        atomicAdd(&osq[c],  q + sh2[c]);
    }
}

__global__ void k_finalize(const float* __restrict__ sum, const float* __restrict__ sq,
                           const float* __restrict__ g, const float* __restrict__ b,
                           float* __restrict__ sc, float* __restrict__ sh) {
    int c = threadIdx.x;
    float mean = sum[c] * (1.f / NN);
    float var  = sq[c] * (1.f / NN) - mean * mean;
    float s = g[c] * rsqrtf(var + EPSB);
    sc[c] = s;
    sh[c] = b[c] - mean * s;
}

// ---------------- final BN2 apply ----------------
__global__ void k_out(float* __restrict__ out) {
    int i = blockIdx.x * blockDim.x + threadIdx.x;   // over NN*HD/4 float4s
    float4 v = ((const float4*)g_h2)[i];
    int c = (i & 31) * 4;
    float4 o;
    o.x = v.x * g_scale2[c  ] + g_shift2[c  ];
    o.y = v.y * g_scale2[c+1] + g_shift2[c+1];
    o.z = v.z * g_scale2[c+2] + g_shift2[c+2];
    o.w = v.w * g_scale2[c+3] + g_shift2[c+3];
    ((float4*)out)[i] = o;
}

// ---------------- host ----------------
extern "C" void kernel_launch(void* const* d_in, const int* in_sizes, int n_in,
                              void* d_out, int out_size) {
    const float*     x   = (const float*)d_in[0];
    const long long* ei  = (const long long*)d_in[1];
    const float*     ea  = (const float*)d_in[2];
    const float*     Wq  = (const float*)d_in[3];  const float* bq  = (const float*)d_in[4];
    const float*     Wk  = (const float*)d_in[5];  const float* bk  = (const float*)d_in[6];
    const float*     Wv  = (const float*)d_in[7];  const float* bv  = (const float*)d_in[8];
    const float*     We  = (const float*)d_in[9];  const float* be  = (const float*)d_in[10];
    const float*     g1  = (const float*)d_in[11]; const float* be1 = (const float*)d_in[12];
    const float*     W1  = (const float*)d_in[13]; const float* b1  = (const float*)d_in[14];
    const float*     W2  = (const float*)d_in[15]; const float* b2  = (const float*)d_in[16];
    const float*     g2  = (const float*)d_in[17]; const float* be2 = (const float*)d_in[18];

    float *pQ, *pK, *pV, *ph0, *pf1, *ph2;
    float *ps1, *pq1, *psc1, *psh1, *ps2, *pq2, *psc2, *psh2;
    cudaGetSymbolAddress((void**)&pQ,   g_Q);
    cudaGetSymbolAddress((void**)&pK,   g_K);
    cudaGetSymbolAddress((void**)&pV,   g_V);
    cudaGetSymbolAddress((void**)&ph0,  g_h0);
    cudaGetSymbolAddress((void**)&pf1,  g_f1);
    cudaGetSymbolAddress((void**)&ph2,  g_h2);
    cudaGetSymbolAddress((void**)&ps1,  g_sum1);
    cudaGetSymbolAddress((void**)&pq1,  g_sq1);
    cudaGetSymbolAddress((void**)&psc1, g_scale1);
    cudaGetSymbolAddress((void**)&psh1, g_shift1);
    cudaGetSymbolAddress((void**)&ps2,  g_sum2);
    cudaGetSymbolAddress((void**)&pq2,  g_sq2);
    cudaGetSymbolAddress((void**)&psc2, g_scale2);
    cudaGetSymbolAddress((void**)&psh2, g_shift2);

    k_zero<<<64, 256>>>();
    k_detect<<<EE / 256, 256>>>(ei);

    dim3 gQKV(HD / 64, NN / 64);
    k_gemm<<<gQKV, 256>>>(x, Wq, bq, pQ, NN, HD, HD, nullptr, nullptr, 0, nullptr, nullptr, nullptr);
    k_gemm<<<gQKV, 256>>>(x, Wk, bk, pK, NN, HD, HD, nullptr, nullptr, 0, nullptr, nullptr, nullptr);
    k_gemm<<<gQKV, 256>>>(x, Wv, bv, pV, NN, HD, HD, nullptr, nullptr, 0, nullptr, nullptr, nullptr);

    k_ebias_hist<<<EE / 256, 256>>>(ea, We, be, ei);
    k_vsum<<<128, 128>>>();
    k_scan<<<1, 1024>>>();
    k_score<<<EE / 8, 256>>>(ei);
    k_row<<<NN / RW, 256>>>(x);

    k_stats<<<128, 256>>>(ph0, ps1, pq1);
    k_finalize<<<1, 128>>>(ps1, pq1, g1, be1, psc1, psh1);

    dim3 gF1(HID / 64, NN / 64);
    k_gemm<<<gF1, 256>>>(ph0, W1, b1, pf1, NN, HID, HD, psc1, psh1, 1, nullptr, nullptr, nullptr);
    dim3 gF2(HD / 64, NN / 64);
    k_gemm<<<gF2, 256>>>(pf1, W2, b2, ph2, NN, HD, HID, nullptr, nullptr, 2, ph0, psc1, psh1);

    k_stats<<<128, 256>>>(ph2, ps2, pq2);
    k_finalize<<<1, 128>>>(ps2, pq2, g2, be2, psc2, psh2);
    k_out<<<(NN * HD / 4) / 256, 256>>>((float*)d_out);
}

// round 2
// speedup vs baseline: 1.3293x; 1.3293x over previous
#include <cuda_runtime.h>
#include <math.h>

#define NN   16384
#define HD   128
#define EE   524288
#define EDD  16
#define HID  256
#define EPSB 1e-5f
#define NEG  0.01f
#define CAP  128
#define RW   8

// ---------------- scratch (device globals; no allocation) ----------------
__device__ float g_Q[NN*HD];
__device__ float g_K[NN*HD];
__device__ float g_V[NN*HD];
__device__ int   g_hist[NN];
__device__ int   g_fill[NN];
__device__ int   g_rowstart[NN+1];
__device__ int   g_cdst[EE];
__device__ float g_cs[EE];
__device__ float g_Vsum[HD];
__device__ float g_h0[NN*HD];
__device__ float g_f1[NN*HID];
__device__ float g_h2[NN*HD];
__device__ float g_sum1[HD], g_sq1[HD], g_scale1[HD], g_shift1[HD];
__device__ float g_sum2[HD], g_sq2[HD], g_scale2[HD], g_shift2[HD];
__device__ int   g_notI64;

// ---------------- helpers ----------------
__device__ __forceinline__ int ld_idx(const long long* ei, int i) {
    return g_notI64 ? ((const int*)ei)[i] : (int)ei[i];
}
__device__ __forceinline__ unsigned f2tf(float f) {
    unsigned u; asm("cvt.rna.tf32.f32 %0, %1;" : "=r"(u) : "f"(f)); return u;
}
__device__ __forceinline__ void mma_tf32(float* c, const unsigned* a, const unsigned* b) {
    asm volatile(
        "mma.sync.aligned.m16n8k8.row.col.f32.tf32.tf32.f32 "
        "{%0,%1,%2,%3}, {%4,%5,%6,%7}, {%8,%9}, {%0,%1,%2,%3};\n"
        : "+f"(c[0]), "+f"(c[1]), "+f"(c[2]), "+f"(c[3])
        : "r"(a[0]), "r"(a[1]), "r"(a[2]), "r"(a[3]), "r"(b[0]), "r"(b[1]));
}

// ---------------- zero scratch ----------------
__global__ void k_zero() {
    int i = blockIdx.x * blockDim.x + threadIdx.x;
    int stride = gridDim.x * blockDim.x;
    for (int j = i; j < NN; j += stride) { g_hist[j] = 0; g_fill[j] = 0; }
    if (i < HD) {
        g_Vsum[i] = 0.f;
        g_sum1[i] = 0.f; g_sq1[i] = 0.f;
        g_sum2[i] = 0.f; g_sq2[i] = 0.f;
    }
    if (i == 0) g_notI64 = 0;
}

// ---------------- detect edge_index dtype ----------------
__global__ void k_detect(const long long* __restrict__ ei) {
    int i = blockIdx.x * blockDim.x + threadIdx.x;
    long long v = ei[i];
    if (v < 0 || v > (NN - 1)) g_notI64 = 1;
}

// ---------------- src histogram ----------------
__global__ void k_hist(const long long* __restrict__ ei) {
    int e = blockIdx.x * blockDim.x + threadIdx.x;
    atomicAdd(&g_hist[ld_idx(ei, e)], 1);
}

// ---------------- Q,K fp32 SIMT GEMM: 128x128 tile, 8x8/thread ----------------
__global__ __launch_bounds__(256) void k_qk(
    const float* __restrict__ x,
    const float* __restrict__ Wq, const float* __restrict__ bq,
    const float* __restrict__ Wk, const float* __restrict__ bk)
{
    __shared__ float As[16][128];   // [k][m]
    __shared__ float Bs[16][128];   // [k][n]
    int t = threadIdx.x;
    int isK = blockIdx.x;
    const float* B    = isK ? Wk : Wq;
    const float* bias = isK ? bk : bq;
    float* C          = isK ? g_K : g_Q;
    int row0 = blockIdx.y * 128;
    int tx = t & 15, ty = t >> 4;
    float acc[8][8] = {};
    int ar = t >> 1;
    int ac = (t & 1) * 8;
    int bkr = t >> 5, bn = (t & 31) * 4;

    for (int k0 = 0; k0 < HD; k0 += 16) {
        float4 a0 = *(const float4*)&x[(row0 + ar) * HD + k0 + ac];
        float4 a1 = *(const float4*)&x[(row0 + ar) * HD + k0 + ac + 4];
        As[ac+0][ar] = a0.x; As[ac+1][ar] = a0.y; As[ac+2][ar] = a0.z; As[ac+3][ar] = a0.w;
        As[ac+4][ar] = a1.x; As[ac+5][ar] = a1.y; As[ac+6][ar] = a1.z; As[ac+7][ar] = a1.w;
        *(float4*)&Bs[bkr][bn]     = *(const float4*)&B[(k0 + bkr) * HD + bn];
        *(float4*)&Bs[bkr + 8][bn] = *(const float4*)&B[(k0 + bkr + 8) * HD + bn];
        __syncthreads();
#pragma unroll
        for (int kk = 0; kk < 16; kk++) {
            float4 am0 = *(const float4*)&As[kk][ty * 8];
            float4 am1 = *(const float4*)&As[kk][ty * 8 + 4];
            float4 bn0 = *(const float4*)&Bs[kk][tx * 4];
            float4 bn1 = *(const float4*)&Bs[kk][tx * 4 + 64];
            float am[8] = {am0.x, am0.y, am0.z, am0.w, am1.x, am1.y, am1.z, am1.w};
            float bv[8] = {bn0.x, bn0.y, bn0.z, bn0.w, bn1.x, bn1.y, bn1.z, bn1.w};
#pragma unroll
            for (int i = 0; i < 8; i++)
#pragma unroll
                for (int j = 0; j < 8; j++)
                    acc[i][j] += am[i] * bv[j];
        }
        __syncthreads();
    }
#pragma unroll
    for (int i = 0; i < 8; i++) {
        int r = row0 + ty * 8 + i;
#pragma unroll
        for (int j = 0; j < 4; j++) {
            C[r * HD + tx * 4 + j]      = acc[i][j]     + bias[tx * 4 + j];
            C[r * HD + 64 + tx * 4 + j] = acc[i][4 + j] + bias[64 + tx * 4 + j];
        }
    }
}

// ---------------- tf32 tensor GEMM: 64x128 block tile ----------------
// C[M,Ncols] = op(A) @ B + bias ; epi: 0 none, 1 relu, 2 residual BN
__global__ __launch_bounds__(256) void k_mma(
    const float* __restrict__ A, const float* __restrict__ B,
    const float* __restrict__ bias, float* __restrict__ C,
    int Ncols, int K,
    const float* __restrict__ sA, const float* __restrict__ hA,
    int epi, const float* __restrict__ res,
    const float* __restrict__ rs, const float* __restrict__ rh)
{
    __shared__ float As[16][68];    // [k][m] tf32 bits
    __shared__ float Bs[16][132];   // [k][n] tf32 bits
    int t = threadIdx.x;
    int row0 = blockIdx.y * 64;
    int col0 = blockIdx.x * 128;
    int wid = t >> 5, lane = t & 31;
    int wm = (wid >> 2) * 32, wn = (wid & 3) * 32;
    int lr = lane & 3, lg = lane >> 2;
    float acc[2][4][4] = {};

    int am_ = t >> 2, ak4 = (t & 3) * 4;

    for (int k0 = 0; k0 < K; k0 += 16) {
        // A tile 64x16
        float4 av = *(const float4*)&A[(row0 + am_) * K + k0 + ak4];
        if (sA) {
            av.x = av.x * sA[k0+ak4  ] + hA[k0+ak4  ];
            av.y = av.y * sA[k0+ak4+1] + hA[k0+ak4+1];
            av.z = av.z * sA[k0+ak4+2] + hA[k0+ak4+2];
            av.w = av.w * sA[k0+ak4+3] + hA[k0+ak4+3];
        }
        As[ak4  ][am_] = __uint_as_float(f2tf(av.x));
        As[ak4+1][am_] = __uint_as_float(f2tf(av.y));
        As[ak4+2][am_] = __uint_as_float(f2tf(av.z));
        As[ak4+3][am_] = __uint_as_float(f2tf(av.w));
        // B tile 16x128
#pragma unroll
        for (int i = 0; i < 2; i++) {
            int idx = t * 2 + i;
            int kr = idx >> 5, nc = (idx & 31) * 4;
            float4 bv = *(const float4*)&B[(k0 + kr) * Ncols + col0 + nc];
            float4 bw;
            bw.x = __uint_as_float(f2tf(bv.x));
            bw.y = __uint_as_float(f2tf(bv.y));
            bw.z = __uint_as_float(f2tf(bv.z));
            bw.w = __uint_as_float(f2tf(bv.w));
            *(float4*)&Bs[kr][nc] = bw;
        }
        __syncthreads();
#pragma unroll
        for (int ks = 0; ks < 16; ks += 8) {
            unsigned a[2][4], b[4][2];
#pragma unroll
            for (int mt = 0; mt < 2; mt++) {
                int m = wm + mt * 16 + lg;
                a[mt][0] = __float_as_uint(As[ks + lr][m]);
                a[mt][1] = __float_as_uint(As[ks + lr][m + 8]);
                a[mt][2] = __float_as_uint(As[ks + 4 + lr][m]);
                a[mt][3] = __float_as_uint(As[ks + 4 + lr][m + 8]);
            }
#pragma unroll
            for (int nt = 0; nt < 4; nt++) {
                int n = wn + nt * 8 + lg;
                b[nt][0] = __float_as_uint(Bs[ks + lr][n]);
                b[nt][1] = __float_as_uint(Bs[ks + 4 + lr][n]);
            }
#pragma unroll
            for (int mt = 0; mt < 2; mt++)
#pragma unroll
                for (int nt = 0; nt < 4; nt++)
                    mma_tf32(acc[mt][nt], a[mt], b[nt]);
        }
        __syncthreads();
    }
    // epilogue
#pragma unroll
    for (int mt = 0; mt < 2; mt++) {
#pragma unroll
        for (int nt = 0; nt < 4; nt++) {
            int r = row0 + wm + mt * 16 + lg;
            int c = col0 + wn + nt * 8 + lr * 2;
#pragma unroll
            for (int h = 0; h < 2; h++) {
                int rr = r + h * 8;
                float v0 = acc[mt][nt][h * 2]     + bias[c];
                float v1 = acc[mt][nt][h * 2 + 1] + bias[c + 1];
                if (epi == 1) { v0 = fmaxf(v0, 0.f); v1 = fmaxf(v1, 0.f); }
                else if (epi == 2) {
                    v0 += res[rr * HD + c]     * rs[c]     + rh[c];
                    v1 += res[rr * HD + c + 1] * rs[c + 1] + rh[c + 1];
                }
                C[rr * Ncols + c]     = v0;
                C[rr * Ncols + c + 1] = v1;
            }
        }
    }
}

// ---------------- exclusive scan over 16384 counts ----------------
__global__ void k_scan() {
    __shared__ int ps[1024];
    int t = threadIdx.x;
    int base = t * 16;
    int loc[16]; int s = 0;
#pragma unroll
    for (int i = 0; i < 16; i++) { loc[i] = g_hist[base + i]; s += loc[i]; }
    ps[t] = s;
    __syncthreads();
    for (int off = 1; off < 1024; off <<= 1) {
        int v = (t >= off) ? ps[t - off] : 0;
        __syncthreads();
        ps[t] += v;
        __syncthreads();
    }
    int run = ps[t] - s;
#pragma unroll
    for (int i = 0; i < 16; i++) { g_rowstart[base + i] = run; run += loc[i]; }
    if (t == 1023) g_rowstart[NN] = run;
}

// ---------------- column sum of V ----------------
__global__ void k_vsum() {
    int c = threadIdx.x;
    int b = blockIdx.x;
    float s = 0.f;
    for (int r = b * 128; r < (b + 1) * 128; r++) s += g_V[r * HD + c];
    atomicAdd(&g_Vsum[c], s);
}

// ---------------- edge bias + scatter into CSR (no Q/K gather here) --------
__global__ void k_scatter(const float* __restrict__ ea, const float* __restrict__ We,
                          const float* __restrict__ be, const long long* __restrict__ ei)
{
    int e = blockIdx.x * blockDim.x + threadIdx.x;
    const float4* a4 = (const float4*)(ea + (size_t)e * EDD);
    float s = be[0];
#pragma unroll
    for (int i = 0; i < 4; i++) {
        float4 v = a4[i];
        s += v.x * We[i*4] + v.y * We[i*4+1] + v.z * We[i*4+2] + v.w * We[i*4+3];
    }
    int src = ld_idx(ei, e);
    int dst = ld_idx(ei, EE + e);
    int pos = g_rowstart[src] + atomicAdd(&g_fill[src], 1);
    g_cdst[pos] = dst;
    g_cs[pos]   = s;          // edge bias; dot added in k_row
}

// ---------------- per-row score+dedup+softmax+gather -> h0 = x + x_new ------
__global__ __launch_bounds__(256) void k_row(const float* __restrict__ x) {
    __shared__ int   sd[RW][CAP];
    __shared__ float ss[RW][CAP];
    __shared__ int   sf[RW][CAP];
    int w = threadIdx.x >> 5, lane = threadIdx.x & 31;
    int row = blockIdx.x * RW + w;
    int start = g_rowstart[row], end = g_rowstart[row + 1];
    int k = end - start;
    const float4* K4 = (const float4*)g_K;
    const float4* V4 = (const float4*)g_V;
    float4 q = ((const float4*)g_Q)[row * 32 + lane];
    float4 acc;
    float invden;

    if (k <= CAP) {
        for (int i = lane; i < k; i += 32) { sd[w][i] = g_cdst[start + i]; ss[w][i] = g_cs[start + i]; }
        __syncwarp();
        // scores: warp per cell, Q row in registers
#pragma unroll 2
        for (int i = 0; i < k; i++) {
            float4 kv = K4[sd[w][i] * 32 + lane];
            float p = q.x*kv.x + q.y*kv.y + q.z*kv.z + q.w*kv.w;
#pragma unroll
            for (int o = 16; o; o >>= 1) p += __shfl_xor_sync(0xffffffffu, p, o);
            if (lane == 0) {
                float s = p + ss[w][i];
                ss[w][i] = (s >= 0.f) ? s : NEG * s;
            }
        }
        __syncwarp();
        // dedup: first-occurrence index per cell
        for (int i = lane; i < k; i += 32) {
            int d = sd[w][i]; int f = 0;
            while (sd[w][f] != d) f++;
            sf[w][i] = f;
        }
        __syncwarp();
        for (int i = lane; i < k; i += 32)
            if (sf[w][i] != i) atomicAdd(&ss[w][sf[w][i]], ss[w][i]);
        __syncwarp();
        float m = 0.f; int cnt = 0;
        for (int i = lane; i < k; i += 32)
            if (sf[w][i] == i) { m = fmaxf(m, ss[w][i]); cnt++; }
#pragma unroll
        for (int o = 16; o; o >>= 1) {
            m = fmaxf(m, __shfl_xor_sync(0xffffffffu, m, o));
            cnt += __shfl_xor_sync(0xffffffffu, cnt, o);
        }
        float em = expf(-m);
        float sumExp = 0.f;
        for (int i = lane; i < k; i += 32) {
            float wv = 0.f;
            if (sf[w][i] == i) {
                float e1 = expf(ss[w][i] - m);
                sumExp += e1;
                wv = e1 - em;
            }
            ss[w][i] = wv;
        }
        __syncwarp();
#pragma unroll
        for (int o = 16; o; o >>= 1) sumExp += __shfl_xor_sync(0xffffffffu, sumExp, o);
        float denom = sumExp + (float)(NN - cnt) * em;
        invden = 1.f / denom;
        float4 vs = ((const float4*)g_Vsum)[lane];
        acc.x = em * vs.x; acc.y = em * vs.y; acc.z = em * vs.z; acc.w = em * vs.w;
        for (int i = 0; i < k; i++) {
            float wv = ss[w][i];
            if (wv != 0.f) {
                float4 v = V4[sd[w][i] * 32 + lane];
                acc.x += wv * v.x; acc.y += wv * v.y; acc.z += wv * v.z; acc.w += wv * v.w;
            }
        }
    } else {
        // rare fallback: O(k^2), warp-uniform
        float m = 0.f; int cnt = 0;
        for (int i = 0; i < k; i++) {
            int d = g_cdst[start + i];
            bool first = true;
            for (int j = 0; j < i; j++) if (g_cdst[start + j] == d) { first = false; break; }
            if (!first) continue;
            float4 kv = K4[d * 32 + lane];
            float p = q.x*kv.x + q.y*kv.y + q.z*kv.z + q.w*kv.w;
#pragma unroll
            for (int o = 16; o; o >>= 1) p += __shfl_xor_sync(0xffffffffu, p, o);
            float v = 0.f;
            for (int j = i; j < k; j++)
                if (g_cdst[start + j] == d) {
                    float s = p + g_cs[start + j];
                    v += (s >= 0.f) ? s : NEG * s;
                }
            cnt++; m = fmaxf(m, v);
        }
        float em = expf(-m);
        float sumExp = 0.f;
        float4 vs = ((const float4*)g_Vsum)[lane];
        acc.x = em * vs.x; acc.y = em * vs.y; acc.z = em * vs.z; acc.w = em * vs.w;
        for (int i = 0; i < k; i++) {
            int d = g_cdst[start + i];
            bool first = true;
            for (int j = 0; j < i; j++) if (g_cdst[start + j] == d) { first = false; break; }
            if (!first) continue;
            float4 kv = K4[d * 32 + lane];
            float p = q.x*kv.x + q.y*kv.y + q.z*kv.z + q.w*kv.w;
#pragma unroll
            for (int o = 16; o; o >>= 1) p += __shfl_xor_sync(0xffffffffu, p, o);
            float v = 0.f;
            for (int j = i; j < k; j++)
                if (g_cdst[start + j] == d) {
                    float s = p + g_cs[start + j];
                    v += (s >= 0.f) ? s : NEG * s;
                }
            float e1 = expf(v - m);
            sumExp += e1;
            float wv = e1 - em;
            float4 vv = V4[d * 32 + lane];
            acc.x += wv * vv.x; acc.y += wv * vv.y; acc.z += wv * vv.z; acc.w += wv * vv.w;
        }
        float denom = sumExp + (float)(NN - cnt) * em;
        invden = 1.f / denom;
    }

    float4 xr = ((const float4*)x)[row * 32 + lane];
    float4 o;
    o.x = xr.x + acc.x * invden;
    o.y = xr.y + acc.y * invden;
    o.z = xr.z + acc.z * invden;
    o.w = xr.w + acc.w * invden;
    ((float4*)g_h0)[row * 32 + lane] = o;
}

// ---------------- batchnorm column stats ----------------
__global__ void k_stats(const float* __restrict__ src, float* __restrict__ osum, float* __restrict__ osq) {
    __shared__ float sh1[128], sh2[128];
    int t = threadIdx.x;
    int c = t & 127, half = t >> 7;
    int r0 = blockIdx.x * 128 + half;
    float s = 0.f, q = 0.f;
    for (int i = 0; i < 64; i++) {
        float v = src[(r0 + 2 * i) * HD + c];
        s += v; q += v * v;
    }
    if (half) { sh1[c] = s; sh2[c] = q; }
    __syncthreads();
    if (!half) {
        atomicAdd(&osum[c], s + sh1[c]);
        atomicAdd(&osq[c],  q + sh2[c]);
    }
}

__global__ void k_finalize(const float* __restrict__ sum, const float* __restrict__ sq,
                           const float* __restrict__ g, const float* __restrict__ b,
                           float* __restrict__ sc, float* __restrict__ sh) {
    int c = threadIdx.x;
    float mean = sum[c] * (1.f / NN);
    float var  = sq[c] * (1.f / NN) - mean * mean;
    float s = g[c] * rsqrtf(var + EPSB);
    sc[c] = s;
    sh[c] = b[c] - mean * s;
}

// ---------------- final BN2 apply ----------------
__global__ void k_out(float* __restrict__ out) {
    int i = blockIdx.x * blockDim.x + threadIdx.x;
    float4 v = ((const float4*)g_h2)[i];
    int c = (i & 31) * 4;
    float4 o;
    o.x = v.x * g_scale2[c  ] + g_shift2[c  ];
    o.y = v.y * g_scale2[c+1] + g_shift2[c+1];
    o.z = v.z * g_scale2[c+2] + g_shift2[c+2];
    o.w = v.w * g_scale2[c+3] + g_shift2[c+3];
    ((float4*)out)[i] = o;
}

// ---------------- host ----------------
extern "C" void kernel_launch(void* const* d_in, const int* in_sizes, int n_in,
                              void* d_out, int out_size) {
    const float*     x   = (const float*)d_in[0];
    const long long* ei  = (const long long*)d_in[1];
    const float*     ea  = (const float*)d_in[2];
    const float*     Wq  = (const float*)d_in[3];  const float* bq  = (const float*)d_in[4];
    const float*     Wk  = (const float*)d_in[5];  const float* bk  = (const float*)d_in[6];
    const float*     Wv  = (const float*)d_in[7];  const float* bv  = (const float*)d_in[8];
    const float*     We  = (const float*)d_in[9];  const float* be  = (const float*)d_in[10];
    const float*     g1  = (const float*)d_in[11]; const float* be1 = (const float*)d_in[12];
    const float*     W1  = (const float*)d_in[13]; const float* b1  = (const float*)d_in[14];
    const float*     W2  = (const float*)d_in[15]; const float* b2  = (const float*)d_in[16];
    const float*     g2  = (const float*)d_in[17]; const float* be2 = (const float*)d_in[18];

    float *pV, *ph0, *pf1, *ph2;
    float *ps1, *pq1, *psc1, *psh1, *ps2, *pq2, *psc2, *psh2;
    cudaGetSymbolAddress((void**)&pV,   g_V);
    cudaGetSymbolAddress((void**)&ph0,  g_h0);
    cudaGetSymbolAddress((void**)&pf1,  g_f1);
    cudaGetSymbolAddress((void**)&ph2,  g_h2);
    cudaGetSymbolAddress((void**)&ps1,  g_sum1);
    cudaGetSymbolAddress((void**)&pq1,  g_sq1);
    cudaGetSymbolAddress((void**)&psc1, g_scale1);
    cudaGetSymbolAddress((void**)&psh1, g_shift1);
    cudaGetSymbolAddress((void**)&ps2,  g_sum2);
    cudaGetSymbolAddress((void**)&pq2,  g_sq2);
    cudaGetSymbolAddress((void**)&psc2, g_scale2);
    cudaGetSymbolAddress((void**)&psh2, g_shift2);

    k_zero<<<64, 256>>>();
    k_detect<<<EE / 256, 256>>>(ei);
    k_hist<<<EE / 256, 256>>>(ei);

    // Q,K in fp32 (score-sensitive); V via tf32 tensor cores
    dim3 gQK(2, NN / 128);
    k_qk<<<gQK, 256>>>(x, Wq, bq, Wk, bk);
    dim3 gV(HD / 128, NN / 64);
    k_mma<<<gV, 256>>>(x, Wv, bv, pV, HD, HD, nullptr, nullptr, 0, nullptr, nullptr, nullptr);

    k_scan<<<1, 1024>>>();
    k_vsum<<<128, 128>>>();
    k_scatter<<<EE / 256, 256>>>(ea, We, be, ei);
    k_row<<<NN / RW, 256>>>(x);

    k_stats<<<128, 256>>>(ph0, ps1, pq1);
    k_finalize<<<1, 128>>>(ps1, pq1, g1, be1, psc1, psh1);

    dim3 gF1(HID / 128, NN / 64);
    k_mma<<<gF1, 256>>>(ph0, W1, b1, pf1, HID, HD, psc1, psh1, 1, nullptr, nullptr, nullptr);
    dim3 gF2(HD / 128, NN / 64);
    k_mma<<<gF2, 256>>>(pf1, W2, b2, ph2, HD, HID, nullptr, nullptr, 2, ph0, psc1, psh1);

    k_stats<<<128, 256>>>(ph2, ps2, pq2);
    k_finalize<<<1, 128>>>(ps2, pq2, g2, be2, psc2, psh2);
    k_out<<<(NN * HD / 4) / 256, 256>>>((float*)d_out);
}